// round 6
// baseline (speedup 1.0000x reference)
#include <cuda_runtime.h>

// Problem constants
#define NB  16
#define NN  1024
#define FIN 64
#define HH  256
#define NEGV  (-9e15f)
#define ALPHA 0.2f

// ---------------- scratch (device globals; no allocation allowed) ----------------
__device__ float g_x  [NB * NN * HH];        // emb output        (16 MB)
__device__ float g_h  [NB * NN * HH];        // per-layer h       (16 MB)
__device__ float g_y  [NB * NN * HH];        // layer-0 output    (16 MB)
__device__ float g_att[(size_t)NB * NN * NN];// attention matrix  (64 MB)
__device__ float g_s1 [NB * NN];
__device__ float g_s2 [NB * NN];
__device__ float g_ps [NB * 8 * HH];         // pooling partial sums
__device__ float g_pm [NB * 8 * HH];         // pooling partial maxes

// ---------------- warp reductions ----------------
__device__ __forceinline__ float warpMax(float v) {
    #pragma unroll
    for (int o = 16; o > 0; o >>= 1) v = fmaxf(v, __shfl_xor_sync(0xFFFFFFFFu, v, o));
    return v;
}
__device__ __forceinline__ float warpSum(float v) {
    #pragma unroll
    for (int o = 16; o > 0; o >>= 1) v += __shfl_xor_sync(0xFFFFFFFFu, v, o);
    return v;
}

// ---------------- generic tiled SGEMM: C = A[M,K] @ B[K,N] (+bias)(relu) ----------------
// BM=128, BN=64, BK=16, 256 threads, 8x4 microtile. Batched via blockIdx.z + strides.
template<bool BIAS, bool RELU>
__global__ __launch_bounds__(256)
void sgemm_kernel(const float* __restrict__ Ag, const float* __restrict__ Bg,
                  const float* __restrict__ bias, float* __restrict__ Cg,
                  int M, int K, int Nn,
                  long long sA, long long sB, long long sC)
{
    constexpr int BM = 128, BN = 64, BK = 16;
    const float* A = Ag + (long long)blockIdx.z * sA;
    const float* B = Bg + (long long)blockIdx.z * sB;
    float*       C = Cg + (long long)blockIdx.z * sC;

    const int bm = blockIdx.y * BM;
    const int bn = blockIdx.x * BN;
    const int tid = threadIdx.x;
    const int tx = tid & 15;      // 0..15 -> 4 cols each
    const int ty = tid >> 4;      // 0..15 -> 8 rows each

    __shared__ __align__(16) float As[BK][BM];
    __shared__ __align__(16) float Bs[BK][BN];

    float acc[8][4];
    #pragma unroll
    for (int i = 0; i < 8; i++)
        #pragma unroll
        for (int j = 0; j < 4; j++) acc[i][j] = 0.f;

    for (int k0 = 0; k0 < K; k0 += BK) {
        // Load A tile (128x16) as float4 along k: 512 float4 / 256 threads = 2 each
        #pragma unroll
        for (int l = 0; l < 2; l++) {
            int e  = tid + l * 256;          // 0..511
            int m  = e >> 2;
            int kc = (e & 3) * 4;
            float4 v = *(const float4*)(A + (long long)(bm + m) * K + k0 + kc);
            As[kc + 0][m] = v.x;
            As[kc + 1][m] = v.y;
            As[kc + 2][m] = v.z;
            As[kc + 3][m] = v.w;
        }
        // Load B tile (16x64) as float4 along n: 256 float4 / 256 threads = 1 each
        {
            int kk = tid >> 4;
            int nc = (tid & 15) * 4;
            *(float4*)&Bs[kk][nc] = *(const float4*)(B + (long long)(k0 + kk) * Nn + bn + nc);
        }
        __syncthreads();

        #pragma unroll
        for (int kk = 0; kk < BK; kk++) {
            float ar[8], br[4];
            float4 a0 = *(const float4*)&As[kk][ty * 8];
            float4 a1 = *(const float4*)&As[kk][ty * 8 + 4];
            float4 b0 = *(const float4*)&Bs[kk][tx * 4];
            ar[0] = a0.x; ar[1] = a0.y; ar[2] = a0.z; ar[3] = a0.w;
            ar[4] = a1.x; ar[5] = a1.y; ar[6] = a1.z; ar[7] = a1.w;
            br[0] = b0.x; br[1] = b0.y; br[2] = b0.z; br[3] = b0.w;
            #pragma unroll
            for (int i = 0; i < 8; i++)
                #pragma unroll
                for (int j = 0; j < 4; j++)
                    acc[i][j] = fmaf(ar[i], br[j], acc[i][j]);
        }
        __syncthreads();
    }

    float4 bb = make_float4(0.f, 0.f, 0.f, 0.f);
    if (BIAS) bb = *(const float4*)(bias + bn + tx * 4);

    #pragma unroll
    for (int i = 0; i < 8; i++) {
        long long m = bm + ty * 8 + i;
        float4 r;
        r.x = acc[i][0] + bb.x;
        r.y = acc[i][1] + bb.y;
        r.z = acc[i][2] + bb.z;
        r.w = acc[i][3] + bb.w;
        if (RELU) {
            r.x = fmaxf(r.x, 0.f); r.y = fmaxf(r.y, 0.f);
            r.z = fmaxf(r.z, 0.f); r.w = fmaxf(r.w, 0.f);
        }
        *(float4*)(C + m * Nn + bn + tx * 4) = r;
    }
}

// ---------------- s1/s2: per-row dot products with a1, a2 ----------------
__global__ __launch_bounds__(256)
void s12_kernel(const float* __restrict__ h, const float* __restrict__ a1,
                const float* __restrict__ a2, float* __restrict__ s1,
                float* __restrict__ s2)
{
    int row = blockIdx.x;
    int t = threadIdx.x;
    float v  = h[(size_t)row * HH + t];
    float p1 = v * a1[t];
    float p2 = v * a2[t];
    p1 = warpSum(p1);
    p2 = warpSum(p2);
    __shared__ float r1[8], r2[8];
    if ((t & 31) == 0) { r1[t >> 5] = p1; r2[t >> 5] = p2; }
    __syncthreads();
    if (t == 0) {
        float t1 = 0.f, t2 = 0.f;
        #pragma unroll
        for (int w = 0; w < 8; w++) { t1 += r1[w]; t2 += r2[w]; }
        s1[row] = t1;
        s2[row] = t2;
    }
}

// ---------------- softmax stats + write normalized attention row ----------------
// One block (256 thr) per (b,i) row; each thread handles 4 j's.
__global__ __launch_bounds__(256)
void stats_att_kernel(const float* __restrict__ adj, const float* __restrict__ s1,
                      const float* __restrict__ s2, float* __restrict__ att)
{
    int bi = blockIdx.x;            // b*NN + i
    int b  = bi >> 10;
    const float* arow = adj + (size_t)bi * NN;   // adj[b,i,:]
    const float* s2b  = s2 + b * NN;
    float s1i = s1[bi];
    int t = threadIdx.x;

    float e[4];
    float mx = -3.4e38f;
    #pragma unroll
    for (int k = 0; k < 4; k++) {
        int j = k * 256 + t;
        float sv = s1i + s2b[j];
        sv = sv >= 0.f ? sv : ALPHA * sv;            // LeakyReLU
        float ev = (arow[j] > 0.f) ? sv : NEGV;      // mask
        e[k] = ev;
        mx = fmaxf(mx, ev);
    }
    __shared__ float redm[8], redz[8];
    float wm = warpMax(mx);
    if ((t & 31) == 0) redm[t >> 5] = wm;
    __syncthreads();
    float m = fmaxf(fmaxf(fmaxf(redm[0], redm[1]), fmaxf(redm[2], redm[3])),
                    fmaxf(fmaxf(redm[4], redm[5]), fmaxf(redm[6], redm[7])));

    float p[4];
    float zs = 0.f;
    #pragma unroll
    for (int k = 0; k < 4; k++) { p[k] = __expf(e[k] - m); zs += p[k]; }
    float ws = warpSum(zs);
    if ((t & 31) == 0) redz[t >> 5] = ws;
    __syncthreads();
    float z = redz[0] + redz[1] + redz[2] + redz[3] +
              redz[4] + redz[5] + redz[6] + redz[7];
    float rz = 1.f / z;

    float* orow = att + (size_t)bi * NN;
    #pragma unroll
    for (int k = 0; k < 4; k++) orow[k * 256 + t] = p[k] * rz;
}

// ---------------- pooling partials: sum & max over 128-row chunks ----------------
__global__ __launch_bounds__(256)
void pool_partial_kernel(const float* __restrict__ x, float* __restrict__ psum,
                         float* __restrict__ pmax)
{
    int b = blockIdx.y, c = blockIdx.x, hh = threadIdx.x;
    const float* xb = x + ((size_t)b * NN + c * 128) * HH + hh;
    float s = 0.f, mx = -3.4e38f;
    #pragma unroll 4
    for (int n = 0; n < 128; n++) {
        float v = xb[(size_t)n * HH];
        s += v;
        mx = fmaxf(mx, v);
    }
    psum[(b * 8 + c) * HH + hh] = s;
    pmax[(b * 8 + c) * HH + hh] = mx;
}

// ---------------- combine pooling + 2-layer MLP head ----------------
__global__ __launch_bounds__(256)
void pool_mlp_kernel(const float* __restrict__ psum, const float* __restrict__ pmax,
                     const float* __restrict__ W1, const float* __restrict__ b1,
                     const float* __restrict__ W2, const float* __restrict__ b2,
                     float* __restrict__ gout)
{
    int b = blockIdx.x, hh = threadIdx.x;
    __shared__ float g[HH], g1[HH];
    float s = 0.f, mx = -3.4e38f;
    #pragma unroll
    for (int c = 0; c < 8; c++) {
        s += psum[(b * 8 + c) * HH + hh];
        mx = fmaxf(mx, pmax[(b * 8 + c) * HH + hh]);
    }
    g[hh] = s * (1.f / (float)NN) + mx;
    __syncthreads();
    float acc = b1[hh];
    #pragma unroll 8
    for (int k = 0; k < HH; k++) acc = fmaf(g[k], W1[k * HH + hh], acc);
    g1[hh] = fmaxf(acc, 0.f);
    __syncthreads();
    float acc2 = b2[hh];
    #pragma unroll 8
    for (int k = 0; k < HH; k++) acc2 = fmaf(g1[k], W2[k * HH + hh], acc2);
    gout[b * HH + hh] = acc2;
}

// ---------------- host orchestration ----------------
extern "C" void kernel_launch(void* const* d_in, const int* in_sizes, int n_in,
                              void* d_out, int out_size)
{
    const float* nf   = (const float*)d_in[0];
    const float* adj  = (const float*)d_in[1];
    const float* embW = (const float*)d_in[2];
    const float* embb = (const float*)d_in[3];
    const float* W0   = (const float*)d_in[4];
    const float* a10  = (const float*)d_in[5];
    const float* a20  = (const float*)d_in[6];
    const float* W1   = (const float*)d_in[7];
    const float* a11  = (const float*)d_in[8];
    const float* a21  = (const float*)d_in[9];
    const float* gW1  = (const float*)d_in[10];
    const float* gb1  = (const float*)d_in[11];
    const float* gW2  = (const float*)d_in[12];
    const float* gb2  = (const float*)d_in[13];
    float* out = (float*)d_out;

    float *xb, *hb, *yb, *attb, *s1b, *s2b, *psb, *pmb;
    cudaGetSymbolAddress((void**)&xb,   g_x);
    cudaGetSymbolAddress((void**)&hb,   g_h);
    cudaGetSymbolAddress((void**)&yb,   g_y);
    cudaGetSymbolAddress((void**)&attb, g_att);
    cudaGetSymbolAddress((void**)&s1b,  g_s1);
    cudaGetSymbolAddress((void**)&s2b,  g_s2);
    cudaGetSymbolAddress((void**)&psb,  g_ps);
    cudaGetSymbolAddress((void**)&pmb,  g_pm);

    const int M = NB * NN;               // 16384
    float* xout = out;                           // [B,N,H] part of output
    float* gout = out + (out_size - NB * HH);    // [B,H]  part of output

    // 1) emb: x = nf @ emb_W + emb_b
    sgemm_kernel<true, false><<<dim3(HH / 64, M / 128, 1), 256>>>(
        nf, embW, embb, xb, M, FIN, HH, 0, 0, 0);

    // ---- GAT layer 0 ----
    sgemm_kernel<false, false><<<dim3(HH / 64, M / 128, 1), 256>>>(
        xb, W0, nullptr, hb, M, HH, HH, 0, 0, 0);
    s12_kernel<<<M, 256>>>(hb, a10, a20, s1b, s2b);
    stats_att_kernel<<<M, 256>>>(adj, s1b, s2b, attb);
    sgemm_kernel<false, true><<<dim3(HH / 64, NN / 128, NB), 256>>>(
        attb, hb, nullptr, yb, NN, NN, HH,
        (long long)NN * NN, (long long)NN * HH, (long long)NN * HH);

    // ---- GAT layer 1 ----
    sgemm_kernel<false, false><<<dim3(HH / 64, M / 128, 1), 256>>>(
        yb, W1, nullptr, hb, M, HH, HH, 0, 0, 0);
    s12_kernel<<<M, 256>>>(hb, a11, a21, s1b, s2b);
    stats_att_kernel<<<M, 256>>>(adj, s1b, s2b, attb);
    sgemm_kernel<false, true><<<dim3(HH / 64, NN / 128, NB), 256>>>(
        attb, hb, nullptr, xout, NN, NN, HH,
        (long long)NN * NN, (long long)NN * HH, (long long)NN * HH);

    // ---- pooling + MLP head ----
    pool_partial_kernel<<<dim3(8, NB), 256>>>(xout, psb, pmb);
    pool_mlp_kernel<<<NB, 256>>>(psb, pmb, gW1, gb1, gW2, gb2, gout);
}

// round 7
// speedup vs baseline: 1.1326x; 1.1326x over previous
#include <cuda_runtime.h>

// Problem constants
#define NB  16
#define NN  1024
#define FIN 64
#define HH  256
#define NEGV  (-9e15f)
#define ALPHA 0.2f

// ---------------- scratch (device globals; no allocation allowed) ----------------
__device__ float g_x  [NB * NN * HH];        // emb output        (16 MB)
__device__ float g_h  [NB * NN * HH];        // per-layer h       (16 MB)
__device__ float g_y  [NB * NN * HH];        // layer-0 output    (16 MB)
__device__ float g_att[(size_t)NB * NN * NN];// attention matrix  (64 MB)
__device__ float g_s1 [NB * NN];
__device__ float g_s2 [NB * NN];
__device__ float g_ps [NB * 8 * HH];         // pooling partial sums
__device__ float g_pm [NB * 8 * HH];         // pooling partial maxes

// ---------------- packed f32x2 helpers (Blackwell FFMA2 path) ----------------
__device__ __forceinline__ unsigned long long pack2(float lo, float hi) {
    unsigned long long r;
    asm("mov.b64 %0, {%1, %2};" : "=l"(r) : "f"(lo), "f"(hi));
    return r;
}
__device__ __forceinline__ void unpack2(unsigned long long v, float& lo, float& hi) {
    asm("mov.b64 {%0, %1}, %2;" : "=f"(lo), "=f"(hi) : "l"(v));
}
__device__ __forceinline__ unsigned long long fma2(unsigned long long a,
                                                   unsigned long long b,
                                                   unsigned long long c) {
    unsigned long long d;
    asm("fma.rn.f32x2 %0, %1, %2, %3;" : "=l"(d) : "l"(a), "l"(b), "l"(c));
    return d;
}

// ---------------- warp reductions ----------------
__device__ __forceinline__ float warpMax(float v) {
    #pragma unroll
    for (int o = 16; o > 0; o >>= 1) v = fmaxf(v, __shfl_xor_sync(0xFFFFFFFFu, v, o));
    return v;
}
__device__ __forceinline__ float warpSum(float v) {
    #pragma unroll
    for (int o = 16; o > 0; o >>= 1) v += __shfl_xor_sync(0xFFFFFFFFu, v, o);
    return v;
}

// ---------------- generic tiled SGEMM: C = A[M,K] @ B[K,N] (+bias)(relu) ----------------
// BM=128, BN=64, BK=16, 256 threads, 8x4 microtile computed as 4 row-pairs of
// packed f32x2 FFMA2. Batched via blockIdx.z + strides.
template<bool BIAS, bool RELU>
__global__ __launch_bounds__(256)
void sgemm_kernel(const float* __restrict__ Ag, const float* __restrict__ Bg,
                  const float* __restrict__ bias, float* __restrict__ Cg,
                  int M, int K, int Nn,
                  long long sA, long long sB, long long sC)
{
    constexpr int BM = 128, BN = 64, BK = 16;
    const float* A = Ag + (long long)blockIdx.z * sA;
    const float* B = Bg + (long long)blockIdx.z * sB;
    float*       C = Cg + (long long)blockIdx.z * sC;

    const int bm = blockIdx.y * BM;
    const int bn = blockIdx.x * BN;
    const int tid = threadIdx.x;
    const int tx = tid & 15;      // 0..15 -> 4 cols each
    const int ty = tid >> 4;      // 0..15 -> 8 rows each (4 packed pairs)

    __shared__ __align__(16) float As[BK][BM];
    __shared__ __align__(16) float Bs[BK][BN];

    // acc2[p][j]: rows (ty*8+2p, ty*8+2p+1), column (tx*4+j), packed f32x2
    unsigned long long acc2[4][4];
    #pragma unroll
    for (int p = 0; p < 4; p++)
        #pragma unroll
        for (int j = 0; j < 4; j++) acc2[p][j] = 0ull;

    for (int k0 = 0; k0 < K; k0 += BK) {
        // Load A tile (128x16) as float4 along k: 512 float4 / 256 threads = 2 each
        #pragma unroll
        for (int l = 0; l < 2; l++) {
            int e  = tid + l * 256;          // 0..511
            int m  = e >> 2;
            int kc = (e & 3) * 4;
            float4 v = *(const float4*)(A + (long long)(bm + m) * K + k0 + kc);
            As[kc + 0][m] = v.x;
            As[kc + 1][m] = v.y;
            As[kc + 2][m] = v.z;
            As[kc + 3][m] = v.w;
        }
        // Load B tile (16x64) as float4 along n: 256 float4 / 256 threads = 1 each
        {
            int kk = tid >> 4;
            int nc = (tid & 15) * 4;
            *(float4*)&Bs[kk][nc] = *(const float4*)(B + (long long)(k0 + kk) * Nn + bn + nc);
        }
        __syncthreads();

        #pragma unroll
        for (int kk = 0; kk < BK; kk++) {
            // A row-pairs arrive pre-packed from shared (8 consecutive rows).
            ulonglong2 va = *(const ulonglong2*)&As[kk][ty * 8];
            ulonglong2 vb = *(const ulonglong2*)&As[kk][ty * 8 + 4];
            unsigned long long aP[4] = { va.x, va.y, vb.x, vb.y };
            // B scalars broadcast into both halves.
            float4 b0 = *(const float4*)&Bs[kk][tx * 4];
            unsigned long long bP[4] = {
                pack2(b0.x, b0.x), pack2(b0.y, b0.y),
                pack2(b0.z, b0.z), pack2(b0.w, b0.w)
            };
            #pragma unroll
            for (int p = 0; p < 4; p++)
                #pragma unroll
                for (int j = 0; j < 4; j++)
                    acc2[p][j] = fma2(aP[p], bP[j], acc2[p][j]);
        }
        __syncthreads();
    }

    float4 bb = make_float4(0.f, 0.f, 0.f, 0.f);
    if (BIAS) bb = *(const float4*)(bias + bn + tx * 4);

    #pragma unroll
    for (int p = 0; p < 4; p++) {
        float lo[4], hi[4];
        #pragma unroll
        for (int j = 0; j < 4; j++) unpack2(acc2[p][j], lo[j], hi[j]);
        long long m0 = bm + ty * 8 + 2 * p;
        float4 r0, r1;
        r0.x = lo[0] + bb.x; r0.y = lo[1] + bb.y; r0.z = lo[2] + bb.z; r0.w = lo[3] + bb.w;
        r1.x = hi[0] + bb.x; r1.y = hi[1] + bb.y; r1.z = hi[2] + bb.z; r1.w = hi[3] + bb.w;
        if (RELU) {
            r0.x = fmaxf(r0.x, 0.f); r0.y = fmaxf(r0.y, 0.f);
            r0.z = fmaxf(r0.z, 0.f); r0.w = fmaxf(r0.w, 0.f);
            r1.x = fmaxf(r1.x, 0.f); r1.y = fmaxf(r1.y, 0.f);
            r1.z = fmaxf(r1.z, 0.f); r1.w = fmaxf(r1.w, 0.f);
        }
        *(float4*)(C + m0 * Nn + bn + tx * 4)       = r0;
        *(float4*)(C + (m0 + 1) * Nn + bn + tx * 4) = r1;
    }
}

// ---------------- s1/s2: per-row dot products with a1, a2 ----------------
__global__ __launch_bounds__(256)
void s12_kernel(const float* __restrict__ h, const float* __restrict__ a1,
                const float* __restrict__ a2, float* __restrict__ s1,
                float* __restrict__ s2)
{
    int row = blockIdx.x;
    int t = threadIdx.x;
    float v  = h[(size_t)row * HH + t];
    float p1 = v * a1[t];
    float p2 = v * a2[t];
    p1 = warpSum(p1);
    p2 = warpSum(p2);
    __shared__ float r1[8], r2[8];
    if ((t & 31) == 0) { r1[t >> 5] = p1; r2[t >> 5] = p2; }
    __syncthreads();
    if (t == 0) {
        float t1 = 0.f, t2 = 0.f;
        #pragma unroll
        for (int w = 0; w < 8; w++) { t1 += r1[w]; t2 += r2[w]; }
        s1[row] = t1;
        s2[row] = t2;
    }
}

// ---------------- softmax stats + write normalized attention row ----------------
// One block (256 thr) per (b,i) row; each thread handles 4 j's.
__global__ __launch_bounds__(256)
void stats_att_kernel(const float* __restrict__ adj, const float* __restrict__ s1,
                      const float* __restrict__ s2, float* __restrict__ att)
{
    int bi = blockIdx.x;            // b*NN + i
    int b  = bi >> 10;
    const float* arow = adj + (size_t)bi * NN;   // adj[b,i,:]
    const float* s2b  = s2 + b * NN;
    float s1i = s1[bi];
    int t = threadIdx.x;

    float e[4];
    float mx = -3.4e38f;
    #pragma unroll
    for (int k = 0; k < 4; k++) {
        int j = k * 256 + t;
        float sv = s1i + s2b[j];
        sv = sv >= 0.f ? sv : ALPHA * sv;            // LeakyReLU
        float ev = (arow[j] > 0.f) ? sv : NEGV;      // mask
        e[k] = ev;
        mx = fmaxf(mx, ev);
    }
    __shared__ float redm[8], redz[8];
    float wm = warpMax(mx);
    if ((t & 31) == 0) redm[t >> 5] = wm;
    __syncthreads();
    float m = fmaxf(fmaxf(fmaxf(redm[0], redm[1]), fmaxf(redm[2], redm[3])),
                    fmaxf(fmaxf(redm[4], redm[5]), fmaxf(redm[6], redm[7])));

    float p[4];
    float zs = 0.f;
    #pragma unroll
    for (int k = 0; k < 4; k++) { p[k] = __expf(e[k] - m); zs += p[k]; }
    float ws = warpSum(zs);
    if ((t & 31) == 0) redz[t >> 5] = ws;
    __syncthreads();
    float z = redz[0] + redz[1] + redz[2] + redz[3] +
              redz[4] + redz[5] + redz[6] + redz[7];
    float rz = 1.f / z;

    float* orow = att + (size_t)bi * NN;
    #pragma unroll
    for (int k = 0; k < 4; k++) orow[k * 256 + t] = p[k] * rz;
}

// ---------------- pooling partials: sum & max over 128-row chunks ----------------
__global__ __launch_bounds__(256)
void pool_partial_kernel(const float* __restrict__ x, float* __restrict__ psum,
                         float* __restrict__ pmax)
{
    int b = blockIdx.y, c = blockIdx.x, hh = threadIdx.x;
    const float* xb = x + ((size_t)b * NN + c * 128) * HH + hh;
    float s = 0.f, mx = -3.4e38f;
    #pragma unroll 4
    for (int n = 0; n < 128; n++) {
        float v = xb[(size_t)n * HH];
        s += v;
        mx = fmaxf(mx, v);
    }
    psum[(b * 8 + c) * HH + hh] = s;
    pmax[(b * 8 + c) * HH + hh] = mx;
}

// ---------------- combine pooling + 2-layer MLP head ----------------
__global__ __launch_bounds__(256)
void pool_mlp_kernel(const float* __restrict__ psum, const float* __restrict__ pmax,
                     const float* __restrict__ W1, const float* __restrict__ b1,
                     const float* __restrict__ W2, const float* __restrict__ b2,
                     float* __restrict__ gout)
{
    int b = blockIdx.x, hh = threadIdx.x;
    __shared__ float g[HH], g1[HH];
    float s = 0.f, mx = -3.4e38f;
    #pragma unroll
    for (int c = 0; c < 8; c++) {
        s += psum[(b * 8 + c) * HH + hh];
        mx = fmaxf(mx, pmax[(b * 8 + c) * HH + hh]);
    }
    g[hh] = s * (1.f / (float)NN) + mx;
    __syncthreads();
    float acc = b1[hh];
    #pragma unroll 8
    for (int k = 0; k < HH; k++) acc = fmaf(g[k], W1[k * HH + hh], acc);
    g1[hh] = fmaxf(acc, 0.f);
    __syncthreads();
    float acc2 = b2[hh];
    #pragma unroll 8
    for (int k = 0; k < HH; k++) acc2 = fmaf(g1[k], W2[k * HH + hh], acc2);
    gout[b * HH + hh] = acc2;
}

// ---------------- host orchestration ----------------
extern "C" void kernel_launch(void* const* d_in, const int* in_sizes, int n_in,
                              void* d_out, int out_size)
{
    const float* nf   = (const float*)d_in[0];
    const float* adj  = (const float*)d_in[1];
    const float* embW = (const float*)d_in[2];
    const float* embb = (const float*)d_in[3];
    const float* W0   = (const float*)d_in[4];
    const float* a10  = (const float*)d_in[5];
    const float* a20  = (const float*)d_in[6];
    const float* W1   = (const float*)d_in[7];
    const float* a11  = (const float*)d_in[8];
    const float* a21  = (const float*)d_in[9];
    const float* gW1  = (const float*)d_in[10];
    const float* gb1  = (const float*)d_in[11];
    const float* gW2  = (const float*)d_in[12];
    const float* gb2  = (const float*)d_in[13];
    float* out = (float*)d_out;

    float *xb, *hb, *yb, *attb, *s1b, *s2b, *psb, *pmb;
    cudaGetSymbolAddress((void**)&xb,   g_x);
    cudaGetSymbolAddress((void**)&hb,   g_h);
    cudaGetSymbolAddress((void**)&yb,   g_y);
    cudaGetSymbolAddress((void**)&attb, g_att);
    cudaGetSymbolAddress((void**)&s1b,  g_s1);
    cudaGetSymbolAddress((void**)&s2b,  g_s2);
    cudaGetSymbolAddress((void**)&psb,  g_ps);
    cudaGetSymbolAddress((void**)&pmb,  g_pm);

    const int M = NB * NN;               // 16384
    float* xout = out;                           // [B,N,H] part of output
    float* gout = out + (out_size - NB * HH);    // [B,H]  part of output

    // 1) emb: x = nf @ emb_W + emb_b
    sgemm_kernel<true, false><<<dim3(HH / 64, M / 128, 1), 256>>>(
        nf, embW, embb, xb, M, FIN, HH, 0, 0, 0);

    // ---- GAT layer 0 ----
    sgemm_kernel<false, false><<<dim3(HH / 64, M / 128, 1), 256>>>(
        xb, W0, nullptr, hb, M, HH, HH, 0, 0, 0);
    s12_kernel<<<M, 256>>>(hb, a10, a20, s1b, s2b);
    stats_att_kernel<<<M, 256>>>(adj, s1b, s2b, attb);
    sgemm_kernel<false, true><<<dim3(HH / 64, NN / 128, NB), 256>>>(
        attb, hb, nullptr, yb, NN, NN, HH,
        (long long)NN * NN, (long long)NN * HH, (long long)NN * HH);

    // ---- GAT layer 1 ----
    sgemm_kernel<false, false><<<dim3(HH / 64, M / 128, 1), 256>>>(
        yb, W1, nullptr, hb, M, HH, HH, 0, 0, 0);
    s12_kernel<<<M, 256>>>(hb, a11, a21, s1b, s2b);
    stats_att_kernel<<<M, 256>>>(adj, s1b, s2b, attb);
    sgemm_kernel<false, true><<<dim3(HH / 64, NN / 128, NB), 256>>>(
        attb, hb, nullptr, xout, NN, NN, HH,
        (long long)NN * NN, (long long)NN * HH, (long long)NN * HH);

    // ---- pooling + MLP head ----
    pool_partial_kernel<<<dim3(8, NB), 256>>>(xout, psb, pmb);
    pool_mlp_kernel<<<NB, 256>>>(psb, pmb, gW1, gb1, gW2, gb2, gout);
}

// round 9
// speedup vs baseline: 2.2620x; 1.9972x over previous
#include <cuda_runtime.h>
#include <cuda_bf16.h>
#include <cstdint>

// Problem constants
#define NB  16
#define NN  1024
#define FIN 64
#define HH  256
#define NEGV  (-9e15f)
#define ALPHA 0.2f

// ---------------- scratch (device globals; no allocation allowed) ----------------
__device__ float g_x  [NB * NN * HH];        // emb output        (16 MB)
__device__ float g_h  [NB * NN * HH];        // per-layer h       (16 MB)
__device__ float g_y  [NB * NN * HH];        // layer-0 output    (16 MB)
__device__ float g_att[(size_t)NB * NN * NN];// attention matrix  (64 MB)
__device__ float g_s1 [NB * NN];
__device__ float g_s2 [NB * NN];
__device__ float g_ps [NB * 8 * HH];         // pooling partial sums
__device__ float g_pm [NB * 8 * HH];         // pooling partial maxes

// ---------------- helpers ----------------
__device__ __forceinline__ uint32_t smem_u32(const void* p) {
    uint32_t a;
    asm("{ .reg .u64 t; cvta.to.shared.u64 t, %1; cvt.u32.u64 %0, t; }" : "=r"(a) : "l"(p));
    return a;
}
__device__ __forceinline__ void split_pair(float x, float y, uint32_t& hi, uint32_t& lo) {
    __nv_bfloat162 h = __floats2bfloat162_rn(x, y);
    float rx = x - __bfloat162float(__low2bfloat16(h));
    float ry = y - __bfloat162float(__high2bfloat16(h));
    __nv_bfloat162 l = __floats2bfloat162_rn(rx, ry);
    hi = *(uint32_t*)&h;
    lo = *(uint32_t*)&l;
}

#define LDSM_X4(r0, r1, r2, r3, addr) \
    asm volatile("ldmatrix.sync.aligned.m8n8.x4.shared.b16 {%0,%1,%2,%3}, [%4];" \
                 : "=r"(r0), "=r"(r1), "=r"(r2), "=r"(r3) : "r"(addr))
#define LDSM_X4T(r0, r1, r2, r3, addr) \
    asm volatile("ldmatrix.sync.aligned.m8n8.x4.trans.shared.b16 {%0,%1,%2,%3}, [%4];" \
                 : "=r"(r0), "=r"(r1), "=r"(r2), "=r"(r3) : "r"(addr))
#define MMA16816(d, a, b) \
    asm volatile("mma.sync.aligned.m16n8k16.row.col.f32.bf16.bf16.f32 " \
                 "{%0,%1,%2,%3}, {%4,%5,%6,%7}, {%8,%9}, {%0,%1,%2,%3};" \
                 : "+f"(d[0]), "+f"(d[1]), "+f"(d[2]), "+f"(d[3]) \
                 : "r"(a[0]), "r"(a[1]), "r"(a[2]), "r"(a[3]), "r"(b[0]), "r"(b[1]))

// ---------------- warp reductions ----------------
__device__ __forceinline__ float warpMax(float v) {
    #pragma unroll
    for (int o = 16; o > 0; o >>= 1) v = fmaxf(v, __shfl_xor_sync(0xFFFFFFFFu, v, o));
    return v;
}
__device__ __forceinline__ float warpSum(float v) {
    #pragma unroll
    for (int o = 16; o > 0; o >>= 1) v += __shfl_xor_sync(0xFFFFFFFFu, v, o);
    return v;
}

// ============================================================================
// Tensor-core GEMM via mma.sync (bf16 split hi/lo, fp32 accum).
// C[M,Nn] = A[M,K] @ B[K,Nn] (+bias)(relu), fp32 in/out.
// Block tile 128x128, BK=32, 256 threads (8 warps, 64x32 warp tiles).
// A smem: [m][k] pad 40 (ldmatrix, conflict-free). B smem: [k][n] pad 136
// (native layout, coalesced fill, ldmatrix.trans, conflict-free).
// Register-staged prefetch of next K-chunk hides LDG latency behind mma.
// Batched via blockIdx.z + strides.
// ============================================================================
#define APAD 40
#define BPAD 136

template<bool BIAS, bool RELU>
__global__ __launch_bounds__(256)
void mma_gemm(const float* __restrict__ Ag, const float* __restrict__ Bg,
              const float* __restrict__ bias, float* __restrict__ Cg,
              int M, int K, int Nn,
              long long sA, long long sB, long long sC)
{
    constexpr int BK = 32;
    __shared__ __align__(16) __nv_bfloat16 sAh[128 * APAD], sAl[128 * APAD];
    __shared__ __align__(16) __nv_bfloat16 sBh[BK * BPAD],  sBl[BK * BPAD];

    const float* A = Ag + (long long)blockIdx.z * sA;
    const float* B = Bg + (long long)blockIdx.z * sB;
    float*       C = Cg + (long long)blockIdx.z * sC;

    const int bm = blockIdx.y * 128;
    const int bn = blockIdx.x * 128;
    const int tid  = threadIdx.x;
    const int lane = tid & 31;
    const int wid  = tid >> 5;
    const int wm = wid & 1, wn = wid >> 1;
    const int m0 = wm * 64, n0 = wn * 32;

    const uint32_t aHi = smem_u32(sAh), aLo = smem_u32(sAl);
    const uint32_t bHi = smem_u32(sBh), bLo = smem_u32(sBl);

    // per-thread ldmatrix base offsets (bytes)
    const uint32_t aoff = (uint32_t)(((m0 + (lane & 7) + ((lane >> 3) & 1) * 8) * APAD
                                     + (lane >> 4) * 8) * 2);
    const uint32_t boff = (uint32_t)((((lane & 7) + ((lane >> 3) & 1) * 8) * BPAD
                                     + n0 + (lane >> 4) * 8) * 2);

    float acc[4][4][4];
    #pragma unroll
    for (int mi = 0; mi < 4; mi++)
        #pragma unroll
        for (int ni = 0; ni < 4; ni++)
            #pragma unroll
            for (int r = 0; r < 4; r++) acc[mi][ni][r] = 0.f;

    float4 aS[4], bS[4];
    const int nIter = K / BK;

    // ---- prologue load of chunk 0 ----
    {
        #pragma unroll
        for (int l = 0; l < 4; l++) {
            int task = tid + (l << 8);
            int row = task >> 3, seg = task & 7;
            aS[l] = *(const float4*)(A + (long long)(bm + row) * K + seg * 4);
        }
        #pragma unroll
        for (int l = 0; l < 4; l++) {
            int task = tid + (l << 8);
            int kr = task >> 5, ns = task & 31;
            bS[l] = *(const float4*)(B + (long long)kr * Nn + bn + ns * 4);
        }
    }

    for (int c = 0; c < nIter; ++c) {
        // ---- convert staged regs -> smem (split bf16) ----
        #pragma unroll
        for (int l = 0; l < 4; l++) {
            int task = tid + (l << 8);
            int row = task >> 3, seg = task & 7;
            uint32_t h0, h1, l0, l1;
            split_pair(aS[l].x, aS[l].y, h0, l0);
            split_pair(aS[l].z, aS[l].w, h1, l1);
            int off = row * APAD + seg * 4;
            *(uint2*)&sAh[off] = make_uint2(h0, h1);
            *(uint2*)&sAl[off] = make_uint2(l0, l1);
        }
        #pragma unroll
        for (int l = 0; l < 4; l++) {
            int task = tid + (l << 8);
            int kr = task >> 5, ns = task & 31;
            uint32_t h0, h1, l0, l1;
            split_pair(bS[l].x, bS[l].y, h0, l0);
            split_pair(bS[l].z, bS[l].w, h1, l1);
            int off = kr * BPAD + ns * 4;
            *(uint2*)&sBh[off] = make_uint2(h0, h1);
            *(uint2*)&sBl[off] = make_uint2(l0, l1);
        }
        __syncthreads();

        // ---- prefetch next chunk into regs (overlaps with mma below) ----
        if (c + 1 < nIter) {
            int k0 = (c + 1) * BK;
            #pragma unroll
            for (int l = 0; l < 4; l++) {
                int task = tid + (l << 8);
                int row = task >> 3, seg = task & 7;
                aS[l] = *(const float4*)(A + (long long)(bm + row) * K + k0 + seg * 4);
            }
            #pragma unroll
            for (int l = 0; l < 4; l++) {
                int task = tid + (l << 8);
                int kr = task >> 5, ns = task & 31;
                bS[l] = *(const float4*)(B + (long long)(k0 + kr) * Nn + bn + ns * 4);
            }
        }

        // ---- 2 x k16 mma steps ----
        #pragma unroll
        for (int kk = 0; kk < BK; kk += 16) {
            uint32_t ah[4][4], al[4][4], bh[4][2], bl[4][2];
            #pragma unroll
            for (int mi = 0; mi < 4; mi++) {
                uint32_t d = (uint32_t)((mi * 16 * APAD + kk) * 2);
                LDSM_X4(ah[mi][0], ah[mi][1], ah[mi][2], ah[mi][3], aHi + aoff + d);
                LDSM_X4(al[mi][0], al[mi][1], al[mi][2], al[mi][3], aLo + aoff + d);
            }
            #pragma unroll
            for (int p = 0; p < 2; p++) {
                uint32_t d = (uint32_t)((kk * BPAD + p * 16) * 2);
                LDSM_X4T(bh[2 * p][0], bh[2 * p][1], bh[2 * p + 1][0], bh[2 * p + 1][1],
                         bHi + boff + d);
                LDSM_X4T(bl[2 * p][0], bl[2 * p][1], bl[2 * p + 1][0], bl[2 * p + 1][1],
                         bLo + boff + d);
            }
            #pragma unroll
            for (int mi = 0; mi < 4; mi++)
                #pragma unroll
                for (int ni = 0; ni < 4; ni++) {
                    MMA16816(acc[mi][ni], ah[mi], bh[ni]);
                    MMA16816(acc[mi][ni], ah[mi], bl[ni]);
                    MMA16816(acc[mi][ni], al[mi], bh[ni]);
                }
        }
        __syncthreads();
    }

    // ---- epilogue: fragment layout -> direct global float2 stores ----
    const int rbase = bm + m0 + (lane >> 2);
    const int cbase = bn + n0 + 2 * (lane & 3);
    #pragma unroll
    for (int ni = 0; ni < 4; ni++) {
        int col = cbase + ni * 8;
        float2 bb = make_float2(0.f, 0.f);
        if (BIAS) bb = *(const float2*)(bias + col);
        #pragma unroll
        for (int mi = 0; mi < 4; mi++) {
            int r0 = rbase + mi * 16;
            float2 v0 = make_float2(acc[mi][ni][0] + bb.x, acc[mi][ni][1] + bb.y);
            float2 v1 = make_float2(acc[mi][ni][2] + bb.x, acc[mi][ni][3] + bb.y);
            if (RELU) {
                v0.x = fmaxf(v0.x, 0.f); v0.y = fmaxf(v0.y, 0.f);
                v1.x = fmaxf(v1.x, 0.f); v1.y = fmaxf(v1.y, 0.f);
            }
            *(float2*)(C + (long long)r0 * Nn + col)       = v0;
            *(float2*)(C + (long long)(r0 + 8) * Nn + col) = v1;
        }
    }
}

// ---------------- s1/s2: per-row dot products with a1, a2 ----------------
__global__ __launch_bounds__(256)
void s12_kernel(const float* __restrict__ h, const float* __restrict__ a1,
                const float* __restrict__ a2, float* __restrict__ s1,
                float* __restrict__ s2)
{
    int row = blockIdx.x;
    int t = threadIdx.x;
    float v  = h[(size_t)row * HH + t];
    float p1 = v * a1[t];
    float p2 = v * a2[t];
    p1 = warpSum(p1);
    p2 = warpSum(p2);
    __shared__ float r1[8], r2[8];
    if ((t & 31) == 0) { r1[t >> 5] = p1; r2[t >> 5] = p2; }
    __syncthreads();
    if (t == 0) {
        float t1 = 0.f, t2 = 0.f;
        #pragma unroll
        for (int w = 0; w < 8; w++) { t1 += r1[w]; t2 += r2[w]; }
        s1[row] = t1;
        s2[row] = t2;
    }
}

// ---------------- softmax stats + write normalized attention row ----------------
__global__ __launch_bounds__(256)
void stats_att_kernel(const float* __restrict__ adj, const float* __restrict__ s1,
                      const float* __restrict__ s2, float* __restrict__ att)
{
    int bi = blockIdx.x;            // b*NN + i
    int b  = bi >> 10;
    const float* arow = adj + (size_t)bi * NN;
    const float* s2b  = s2 + b * NN;
    float s1i = s1[bi];
    int t = threadIdx.x;

    float e[4];
    float mx = -3.4e38f;
    #pragma unroll
    for (int k = 0; k < 4; k++) {
        int j = k * 256 + t;
        float sv = s1i + s2b[j];
        sv = sv >= 0.f ? sv : ALPHA * sv;
        float ev = (arow[j] > 0.f) ? sv : NEGV;
        e[k] = ev;
        mx = fmaxf(mx, ev);
    }
    __shared__ float redm[8], redz[8];
    float wm = warpMax(mx);
    if ((t & 31) == 0) redm[t >> 5] = wm;
    __syncthreads();
    float m = fmaxf(fmaxf(fmaxf(redm[0], redm[1]), fmaxf(redm[2], redm[3])),
                    fmaxf(fmaxf(redm[4], redm[5]), fmaxf(redm[6], redm[7])));

    float p[4];
    float zs = 0.f;
    #pragma unroll
    for (int k = 0; k < 4; k++) { p[k] = __expf(e[k] - m); zs += p[k]; }
    float ws = warpSum(zs);
    if ((t & 31) == 0) redz[t >> 5] = ws;
    __syncthreads();
    float z = redz[0] + redz[1] + redz[2] + redz[3] +
              redz[4] + redz[5] + redz[6] + redz[7];
    float rz = 1.f / z;

    float* orow = att + (size_t)bi * NN;
    #pragma unroll
    for (int k = 0; k < 4; k++) orow[k * 256 + t] = p[k] * rz;
}

// ---------------- pooling partials: sum & max over 128-row chunks ----------------
__global__ __launch_bounds__(256)
void pool_partial_kernel(const float* __restrict__ x, float* __restrict__ psum,
                         float* __restrict__ pmax)
{
    int b = blockIdx.y, c = blockIdx.x, hh = threadIdx.x;
    const float* xb = x + ((size_t)b * NN + c * 128) * HH + hh;
    float s = 0.f, mx = -3.4e38f;
    #pragma unroll 4
    for (int n = 0; n < 128; n++) {
        float v = xb[(size_t)n * HH];
        s += v;
        mx = fmaxf(mx, v);
    }
    psum[(b * 8 + c) * HH + hh] = s;
    pmax[(b * 8 + c) * HH + hh] = mx;
}

// ---------------- combine pooling + 2-layer MLP head ----------------
__global__ __launch_bounds__(256)
void pool_mlp_kernel(const float* __restrict__ psum, const float* __restrict__ pmax,
                     const float* __restrict__ W1, const float* __restrict__ b1,
                     const float* __restrict__ W2, const float* __restrict__ b2,
                     float* __restrict__ gout)
{
    int b = blockIdx.x, hh = threadIdx.x;
    __shared__ float g[HH], g1[HH];
    float s = 0.f, mx = -3.4e38f;
    #pragma unroll
    for (int c = 0; c < 8; c++) {
        s += psum[(b * 8 + c) * HH + hh];
        mx = fmaxf(mx, pmax[(b * 8 + c) * HH + hh]);
    }
    g[hh] = s * (1.f / (float)NN) + mx;
    __syncthreads();
    float acc = b1[hh];
    #pragma unroll 8
    for (int k = 0; k < HH; k++) acc = fmaf(g[k], W1[k * HH + hh], acc);
    g1[hh] = fmaxf(acc, 0.f);
    __syncthreads();
    float acc2 = b2[hh];
    #pragma unroll 8
    for (int k = 0; k < HH; k++) acc2 = fmaf(g1[k], W2[k * HH + hh], acc2);
    gout[b * HH + hh] = acc2;
}

// ---------------- host orchestration ----------------
extern "C" void kernel_launch(void* const* d_in, const int* in_sizes, int n_in,
                              void* d_out, int out_size)
{
    const float* nf   = (const float*)d_in[0];
    const float* adj  = (const float*)d_in[1];
    const float* embW = (const float*)d_in[2];
    const float* embb = (const float*)d_in[3];
    const float* W0   = (const float*)d_in[4];
    const float* a10  = (const float*)d_in[5];
    const float* a20  = (const float*)d_in[6];
    const float* W1   = (const float*)d_in[7];
    const float* a11  = (const float*)d_in[8];
    const float* a21  = (const float*)d_in[9];
    const float* gW1  = (const float*)d_in[10];
    const float* gb1  = (const float*)d_in[11];
    const float* gW2  = (const float*)d_in[12];
    const float* gb2  = (const float*)d_in[13];
    float* out = (float*)d_out;

    float *xb, *hb, *yb, *attb, *s1b, *s2b, *psb, *pmb;
    cudaGetSymbolAddress((void**)&xb,   g_x);
    cudaGetSymbolAddress((void**)&hb,   g_h);
    cudaGetSymbolAddress((void**)&yb,   g_y);
    cudaGetSymbolAddress((void**)&attb, g_att);
    cudaGetSymbolAddress((void**)&s1b,  g_s1);
    cudaGetSymbolAddress((void**)&s2b,  g_s2);
    cudaGetSymbolAddress((void**)&psb,  g_ps);
    cudaGetSymbolAddress((void**)&pmb,  g_pm);

    const int M = NB * NN;               // 16384
    float* xout = out;                           // [B,N,H] part of output
    float* gout = out + (out_size - NB * HH);    // [B,H]  part of output

    // 1) emb: x = nf @ emb_W + emb_b   (M=16384, K=64, N=256)
    mma_gemm<true, false><<<dim3(HH / 128, M / 128, 1), 256>>>(
        nf, embW, embb, xb, M, FIN, HH, 0, 0, 0);

    // ---- GAT layer 0 ----
    mma_gemm<false, false><<<dim3(HH / 128, M / 128, 1), 256>>>(
        xb, W0, nullptr, hb, M, HH, HH, 0, 0, 0);
    s12_kernel<<<M, 256>>>(hb, a10, a20, s1b, s2b);
    stats_att_kernel<<<M, 256>>>(adj, s1b, s2b, attb);
    mma_gemm<false, true><<<dim3(HH / 128, NN / 128, NB), 256>>>(
        attb, hb, nullptr, yb, NN, NN, HH,
        (long long)NN * NN, (long long)NN * HH, (long long)NN * HH);

    // ---- GAT layer 1 ----
    mma_gemm<false, false><<<dim3(HH / 128, M / 128, 1), 256>>>(
        yb, W1, nullptr, hb, M, HH, HH, 0, 0, 0);
    s12_kernel<<<M, 256>>>(hb, a11, a21, s1b, s2b);
    stats_att_kernel<<<M, 256>>>(adj, s1b, s2b, attb);
    mma_gemm<false, true><<<dim3(HH / 128, NN / 128, NB), 256>>>(
        attb, hb, nullptr, xout, NN, NN, HH,
        (long long)NN * NN, (long long)NN * HH, (long long)NN * HH);

    // ---- pooling + MLP head ----
    pool_partial_kernel<<<dim3(8, NB), 256>>>(xout, psb, pmb);
    pool_mlp_kernel<<<NB, 256>>>(psb, pmb, gW1, gb1, gW2, gb2, gout);
}